// round 2
// baseline (speedup 1.0000x reference)
#include <cuda_runtime.h>
#include <math.h>

// ---------------- scratch (static device memory; no allocation) ----------------
__device__ float g_HS[50000 * 128];     // transformed source-node features
__device__ float g_HD[50000 * 128];     // transformed dest-node features
__device__ float g_EXPV[500000 * 4];    // per-edge exp(logit) per head
__device__ float g_SEGSUM[50000 * 4];   // per-dst-node softmax denominators
__device__ float g_GATE2[250000 * 128]; // per-edge continuous gate (type 2)
__device__ float g_GTAB[80 * 128];      // categorical gate table (type 0)
__device__ float g_ACC[85000 * 128];    // acc: chem[0..50000) gene[..80000) path[..85000)

__device__ __forceinline__ void red_add_v4(float* p, float4 v) {
    asm volatile("red.global.add.v4.f32 [%0], {%1,%2,%3,%4};"
                 :: "l"(p), "f"(v.x), "f"(v.y), "f"(v.z), "f"(v.w) : "memory");
}

// ---------------- GEMM: Y[N,128] = X[N,128] @ W[128,128] + b ----------------
__global__ void __launch_bounds__(256) gemm128k(
    const float* __restrict__ X, const float* __restrict__ W,
    const float* __restrict__ bias, float* __restrict__ Y, int nrows)
{
    __shared__ float Xs[64 * 128];
    int tid = threadIdx.x;
    int row0 = blockIdx.x * 64;
    const float4* X4 = (const float4*)X;
    float4* Xs4 = (float4*)Xs;
#pragma unroll
    for (int i = 0; i < 8; i++) {
        int idx = tid + 256 * i;          // 0..2047 float4s
        int r = idx >> 5;
        int gr = row0 + r;
        float4 v = make_float4(0.f, 0.f, 0.f, 0.f);
        if (gr < nrows) v = X4[(size_t)gr * 32 + (idx & 31)];
        Xs4[idx] = v;
    }
    __syncthreads();
    int cid = tid & 31;   // column group: cols [4*cid, 4*cid+4)
    int rid = tid >> 5;   // row group: rows [8*rid, 8*rid+8)
    float4 b4 = ((const float4*)bias)[cid];
    float acc[8][4];
#pragma unroll
    for (int i = 0; i < 8; i++) {
        acc[i][0] = b4.x; acc[i][1] = b4.y; acc[i][2] = b4.z; acc[i][3] = b4.w;
    }
    const float* Xrow = Xs + rid * 8 * 128;
    const float4* Wc = (const float4*)W + cid;
#pragma unroll 2
    for (int k = 0; k < 128; k++) {
        float4 w4 = __ldg(Wc + k * 32);
#pragma unroll
        for (int i = 0; i < 8; i++) {
            float a = Xrow[i * 128 + k];
            acc[i][0] = fmaf(a, w4.x, acc[i][0]);
            acc[i][1] = fmaf(a, w4.y, acc[i][1]);
            acc[i][2] = fmaf(a, w4.z, acc[i][2]);
            acc[i][3] = fmaf(a, w4.w, acc[i][3]);
        }
    }
#pragma unroll
    for (int i = 0; i < 8; i++) {
        int gr = row0 + rid * 8 + i;
        if (gr < nrows)
            ((float4*)Y)[(size_t)gr * 32 + cid] =
                make_float4(acc[i][0], acc[i][1], acc[i][2], acc[i][3]);
    }
}

// ---------------- edge-type-2 continuous gate ----------------
// G = sigmoid(gelu(cp @ W1 + b1) @ W2 + b2), cp is [E,3].
__global__ void __launch_bounds__(256) gate2k(
    const float* __restrict__ cp, const float* __restrict__ W1,
    const float* __restrict__ b1, const float* __restrict__ W2,
    const float* __restrict__ b2, float* __restrict__ G, int E)
{
    __shared__ float Hs[64 * 128];
    int tid = threadIdx.x;
    int e0 = blockIdx.x * 64;
#pragma unroll
    for (int i = 0; i < 32; i++) {
        int idx = tid + 256 * i;          // 0..8191
        int r = idx >> 7;
        int c = idx & 127;
        int ge = e0 + r;
        float v = 0.f;
        if (ge < E) {
            float x0 = cp[ge * 3 + 0], x1 = cp[ge * 3 + 1], x2 = cp[ge * 3 + 2];
            float h = fmaf(x0, W1[c], fmaf(x1, W1[128 + c], fmaf(x2, W1[256 + c], b1[c])));
            v = 0.5f * h * (1.0f + erff(h * 0.7071067811865476f));
        }
        Hs[idx] = v;
    }
    __syncthreads();
    int cid = tid & 31, rid = tid >> 5;
    float4 b4 = ((const float4*)b2)[cid];
    float acc[8][4];
#pragma unroll
    for (int i = 0; i < 8; i++) {
        acc[i][0] = b4.x; acc[i][1] = b4.y; acc[i][2] = b4.z; acc[i][3] = b4.w;
    }
    const float* Hrow = Hs + rid * 8 * 128;
    const float4* Wc = (const float4*)W2 + cid;
#pragma unroll 2
    for (int k = 0; k < 128; k++) {
        float4 w4 = __ldg(Wc + k * 32);
#pragma unroll
        for (int i = 0; i < 8; i++) {
            float a = Hrow[i * 128 + k];
            acc[i][0] = fmaf(a, w4.x, acc[i][0]);
            acc[i][1] = fmaf(a, w4.y, acc[i][1]);
            acc[i][2] = fmaf(a, w4.z, acc[i][2]);
            acc[i][3] = fmaf(a, w4.w, acc[i][3]);
        }
    }
#pragma unroll
    for (int i = 0; i < 8; i++) {
        int ge = e0 + rid * 8 + i;
        if (ge < E) {
            float4 o;
            o.x = 1.f / (1.f + expf(-acc[i][0]));
            o.y = 1.f / (1.f + expf(-acc[i][1]));
            o.z = 1.f / (1.f + expf(-acc[i][2]));
            o.w = 1.f / (1.f + expf(-acc[i][3]));
            ((float4*)G)[(size_t)ge * 32 + cid] = o;
        }
    }
}

// ---------------- categorical gate table (80 combos x 128) ----------------
__global__ void gtabk(const float* __restrict__ te, const float* __restrict__ se,
                      const float* __restrict__ Wg, const float* __restrict__ bg)
{
    int c = threadIdx.x;   // 128
    int r = blockIdx.x;    // 80
    int a = r >> 3, b = r & 7;
    float s = bg[c];
#pragma unroll 8
    for (int j = 0; j < 32; j++) s = fmaf(te[a * 32 + j], Wg[j * 128 + c], s);
#pragma unroll 8
    for (int j = 0; j < 32; j++) s = fmaf(se[b * 32 + j], Wg[(32 + j) * 128 + c], s);
    g_GTAB[r * 128 + c] = 1.f / (1.f + expf(-s));
}

// ---------------- pass A: per-edge logits -> exp, segment sums ----------------
__global__ void __launch_bounds__(256) passA(
    const float* __restrict__ HS, const float* __restrict__ HD,
    const int* __restrict__ src, const int* __restrict__ dst,
    const float* __restrict__ attn_t, const float* __restrict__ gate,
    const int* __restrict__ cg, float* __restrict__ expv,
    float* __restrict__ segsum, int E)
{
    int e = (int)((blockIdx.x * (size_t)blockDim.x + threadIdx.x) >> 5);
    if (e >= E) return;
    int lane = threadIdx.x & 31;
    int s = src[e], d = dst[e];
    float4 ms = ((const float4*)(HS + (size_t)s * 128))[lane];
    float4 md = ((const float4*)(HD + (size_t)d * 128))[lane];
    if (gate) {
        float4 g = ((const float4*)(gate + (size_t)e * 128))[lane];
        ms.x *= g.x; ms.y *= g.y; ms.z *= g.z; ms.w *= g.w;
    } else if (cg) {
        int a = cg[2 * e], b = cg[2 * e + 1];
        float4 g = ((const float4*)(g_GTAB + (a * 8 + b) * 128))[lane];
        ms.x *= g.x; ms.y *= g.y; ms.z *= g.z; ms.w *= g.w;
    }
    float4 at = ((const float4*)attn_t)[lane];
    float p = (ms.x + md.x) * at.x + (ms.y + md.y) * at.y +
              (ms.z + md.z) * at.z + (ms.w + md.w) * at.w;
    p += __shfl_xor_sync(0xffffffffu, p, 4);
    p += __shfl_xor_sync(0xffffffffu, p, 2);
    p += __shfl_xor_sync(0xffffffffu, p, 1);
    float h0 = __shfl_sync(0xffffffffu, p, 0);
    float h1 = __shfl_sync(0xffffffffu, p, 8);
    float h2 = __shfl_sync(0xffffffffu, p, 16);
    float h3 = __shfl_sync(0xffffffffu, p, 24);
    if (lane == 0) {
        float4 ex;
        ex.x = expf(h0 > 0.f ? h0 : 0.2f * h0);
        ex.y = expf(h1 > 0.f ? h1 : 0.2f * h1);
        ex.z = expf(h2 > 0.f ? h2 : 0.2f * h2);
        ex.w = expf(h3 > 0.f ? h3 : 0.2f * h3);
        ((float4*)expv)[e] = ex;
        red_add_v4(segsum + (size_t)d * 4, ex);
    }
}

// ---------------- pass B: alpha * gated_ms scattered into acc ----------------
__global__ void __launch_bounds__(256) passB(
    const float* __restrict__ HS,
    const int* __restrict__ src, const int* __restrict__ dst,
    const float* __restrict__ gate, const int* __restrict__ cg,
    const float* __restrict__ expv, const float* __restrict__ segsum,
    float* __restrict__ acc, int E)
{
    int e = (int)((blockIdx.x * (size_t)blockDim.x + threadIdx.x) >> 5);
    if (e >= E) return;
    int lane = threadIdx.x & 31;
    int s = src[e], d = dst[e];
    int h = lane >> 3;
    float al = expv[4 * e + h] / segsum[(size_t)d * 4 + h];
    float4 ms = ((const float4*)(HS + (size_t)s * 128))[lane];
    if (gate) {
        float4 g = ((const float4*)(gate + (size_t)e * 128))[lane];
        ms.x *= g.x; ms.y *= g.y; ms.z *= g.z; ms.w *= g.w;
    } else if (cg) {
        int a = cg[2 * e], b = cg[2 * e + 1];
        float4 g = ((const float4*)(g_GTAB + (a * 8 + b) * 128))[lane];
        ms.x *= g.x; ms.y *= g.y; ms.z *= g.z; ms.w *= g.w;
    }
    float4 o = make_float4(al * ms.x, al * ms.y, al * ms.z, al * ms.w);
    red_add_v4(acc + (size_t)d * 128 + lane * 4, o);
}

// ---------------- disease output: pure bias broadcast ----------------
__global__ void biasfill(float* __restrict__ out, const float* __restrict__ b, int n)
{
    int i = blockIdx.x * blockDim.x + threadIdx.x;
    if (i < n * 128) out[i] = b[i & 127];
}

// ---------------- launch ----------------
extern "C" void kernel_launch(void* const* d_in, const int* in_sizes, int n_in,
                              void* d_out, int out_size)
{
    // ---- input slot mapping: autodetect between two plausible orders ----
    // Layout A (reference signature order):
    //   0-3 x_*, 4 Wsrc, 5 bsrc, 6 Wdst, 7 bdst, 8 attn, 9 type_emb, 10 subj_emb,
    //   11 Wg, 12 bg, 13 W1c, 14 b1c, 15 W2c, 16 b2c, 17 Wout, 18 bout, 19 cp_attr,
    //   20 src0, 21 dst0, 22 src1, 23 dst1, 24 src2, 25 dst2, 26 src3, 27 dst3, 28 cg_attr
    // Layout B (setup_inputs dict order):
    //   0-3 x_*, 4 src0, 5 dst0, 6 src1, 7 dst1, 8 src2, 9 dst2, 10 src3, 11 dst3,
    //   12 cg_attr, 13 cp_attr, 14 Wsrc, 15 bsrc, 16 Wdst, 17 bdst, 18 attn,
    //   19 type_emb, 20 subj_emb, 21 Wg, 22 bg, 23 W1c, 24 b1c, 25 W2c, 26 b2c,
    //   27 Wout, 28 bout
    int iWsrc, ibsrc, iWdst, ibdst, iattn, itemb, isemb, iWg, ibg, iW1c, ib1c,
        iW2c, ib2c, iWout, ibout, icp, icg;
    int isrc[4], idst[4];
    if (in_sizes[4] == 65536) {            // layout A: Wsrc at slot 4
        iWsrc = 4; ibsrc = 5; iWdst = 6; ibdst = 7; iattn = 8; itemb = 9; isemb = 10;
        iWg = 11; ibg = 12; iW1c = 13; ib1c = 14; iW2c = 15; ib2c = 16;
        iWout = 17; ibout = 18; icp = 19;
        isrc[0] = 20; idst[0] = 21; isrc[1] = 22; idst[1] = 23;
        isrc[2] = 24; idst[2] = 25; isrc[3] = 26; idst[3] = 27; icg = 28;
    } else {                               // layout B: src0 at slot 4
        isrc[0] = 4; idst[0] = 5; isrc[1] = 6; idst[1] = 7;
        isrc[2] = 8; idst[2] = 9; isrc[3] = 10; idst[3] = 11;
        icg = 12; icp = 13;
        iWsrc = 14; ibsrc = 15; iWdst = 16; ibdst = 17; iattn = 18;
        itemb = 19; isemb = 20; iWg = 21; ibg = 22; iW1c = 23; ib1c = 24;
        iW2c = 25; ib2c = 26; iWout = 27; ibout = 28;
    }

    const float* x[4]  = {(const float*)d_in[0], (const float*)d_in[1],
                          (const float*)d_in[2], (const float*)d_in[3]};
    const float* Wsrc  = (const float*)d_in[iWsrc];
    const float* bsrc  = (const float*)d_in[ibsrc];
    const float* Wdst  = (const float*)d_in[iWdst];
    const float* bdst  = (const float*)d_in[ibdst];
    const float* attn  = (const float*)d_in[iattn];
    const float* temb  = (const float*)d_in[itemb];
    const float* semb  = (const float*)d_in[isemb];
    const float* Wg    = (const float*)d_in[iWg];
    const float* bg    = (const float*)d_in[ibg];
    const float* W1c   = (const float*)d_in[iW1c];
    const float* b1c   = (const float*)d_in[ib1c];
    const float* W2c   = (const float*)d_in[iW2c];
    const float* b2c   = (const float*)d_in[ib2c];
    const float* Wout  = (const float*)d_in[iWout];
    const float* bout  = (const float*)d_in[ibout];
    const float* cp    = (const float*)d_in[icp];
    const int* srcp[4] = {(const int*)d_in[isrc[0]], (const int*)d_in[isrc[1]],
                          (const int*)d_in[isrc[2]], (const int*)d_in[isrc[3]]};
    const int* dstp[4] = {(const int*)d_in[idst[0]], (const int*)d_in[idst[1]],
                          (const int*)d_in[idst[2]], (const int*)d_in[idst[3]]};
    const int* cg      = (const int*)d_in[icg];
    float* out = (float*)d_out;

    int Nn[4] = {in_sizes[0] / 128, in_sizes[1] / 128, in_sizes[2] / 128, in_sizes[3] / 128};
    int Ee[4] = {in_sizes[isrc[0]], in_sizes[isrc[1]], in_sizes[isrc[2]], in_sizes[isrc[3]]};
    int sidx[4] = {0, 1, 0, 2};  // src node type per edge type
    int didx[4] = {1, 0, 3, 1};  // dst node type per edge type

    float *HS, *HD, *EXPV, *SEG, *G2, *ACC;
    cudaGetSymbolAddress((void**)&HS, g_HS);
    cudaGetSymbolAddress((void**)&HD, g_HD);
    cudaGetSymbolAddress((void**)&EXPV, g_EXPV);
    cudaGetSymbolAddress((void**)&SEG, g_SEGSUM);
    cudaGetSymbolAddress((void**)&G2, g_GATE2);
    cudaGetSymbolAddress((void**)&ACC, g_ACC);

    // acc regions by node type (disease never a dst)
    float* accp[4];
    accp[0] = ACC;
    accp[1] = ACC + (size_t)Nn[0] * 128;
    accp[2] = nullptr;
    accp[3] = ACC + (size_t)(Nn[0] + Nn[1]) * 128;

    cudaMemsetAsync(ACC, 0, (size_t)(Nn[0] + Nn[1] + Nn[3]) * 128 * sizeof(float));
    gtabk<<<80, 128>>>(temb, semb, Wg, bg);
    gate2k<<<(Ee[2] + 63) / 64, 256>>>(cp, W1c, b1c, W2c, b2c, G2, Ee[2]);

    for (int t = 0; t < 4; t++) {
        int s = sidx[t], d = didx[t];
        gemm128k<<<(Nn[s] + 63) / 64, 256>>>(x[s], Wsrc + t * 16384, bsrc + t * 128, HS, Nn[s]);
        gemm128k<<<(Nn[d] + 63) / 64, 256>>>(x[d], Wdst + t * 16384, bdst + t * 128, HD, Nn[d]);
        cudaMemsetAsync(SEG, 0, (size_t)Nn[d] * 4 * sizeof(float));
        const float* gate = (t == 2) ? G2 : nullptr;
        const int* cgp = (t == 0) ? cg : nullptr;
        int blocksE = (Ee[t] + 7) / 8;
        passA<<<blocksE, 256>>>(HS, HD, srcp[t], dstp[t], attn + t * 128,
                                gate, cgp, EXPV, SEG, Ee[t]);
        passB<<<blocksE, 256>>>(HS, srcp[t], dstp[t], gate, cgp, EXPV, SEG,
                                accp[d], Ee[t]);
    }

    // outputs, tuple order: chemical, gene, disease, pathway
    float* o_chem = out;
    float* o_gene = o_chem + (size_t)Nn[0] * 128;
    float* o_dis  = o_gene + (size_t)Nn[1] * 128;
    float* o_path = o_dis + (size_t)Nn[2] * 128;
    gemm128k<<<(Nn[0] + 63) / 64, 256>>>(accp[0], Wout,             bout,       o_chem, Nn[0]);
    gemm128k<<<(Nn[1] + 63) / 64, 256>>>(accp[1], Wout + 16384,     bout + 128, o_gene, Nn[1]);
    biasfill<<<(Nn[2] * 128 + 255) / 256, 256>>>(o_dis, bout + 256, Nn[2]);
    gemm128k<<<(Nn[3] + 63) / 64, 256>>>(accp[3], Wout + 3 * 16384, bout + 384, o_path, Nn[3]);
}

// round 4
// speedup vs baseline: 1.0017x; 1.0017x over previous
#include <cuda_runtime.h>
#include <cuda_bf16.h>
#include <mma.h>
#include <math.h>
#include <stdint.h>

using namespace nvcuda;

// ---------------- static scratch ----------------
__device__ float g_H[140000 * 128];     // HS tables: t0@0(50k) t1@50k(30k) t2@80k(50k) t3@130k(10k)
__device__ float g_G2[250000 * 128];    // per-edge continuous gate (t2)
__device__ float g_P2[50000 * 128];     // HS2 * attn2 (pointwise)
__device__ float g_EXPV[1500000 * 4];   // per-edge exp(logit) per head (all 4 types)
__device__ float g_SEG[4 * 50000 * 4];  // per-(type,dst) softmax denominators
__device__ float g_ACC[85000 * 128];    // chem[0,50k) gene[50k,80k) path[80k,85k)
__device__ float g_GTAB[80 * 128];      // categorical gate table
__device__ float g_GTA0[80 * 128];      // gate table * attn0
__device__ float g_AS[2 * 50000 * 4];   // per-src attn dots (t1 @0, t3 @200000)
__device__ float g_AD[4 * 50000 * 4];   // per-dst attn dots, per edge type
__device__ float g_WA[4 * 128 * 4];     // Wdst collapsed with attn
__device__ float g_BA[4 * 4];
__device__ __nv_bfloat16 g_WTh[8 * 16384]; // transposed weights, bf16 hi
__device__ __nv_bfloat16 g_WTl[8 * 16384]; // transposed weights, bf16 lo

__device__ __forceinline__ void red_add_v4(float* p, float4 v) {
    asm volatile("red.global.add.v4.f32 [%0], {%1,%2,%3,%4};"
                 :: "l"(p), "f"(v.x), "f"(v.y), "f"(v.z), "f"(v.w) : "memory");
}

__device__ __forceinline__ void split_pack(float4 v, uint2& hu, uint2& lu) {
    __nv_bfloat16 hx = __float2bfloat16(v.x), hy = __float2bfloat16(v.y);
    __nv_bfloat16 hz = __float2bfloat16(v.z), hw = __float2bfloat16(v.w);
    hu.x = ((uint32_t)__bfloat16_as_ushort(hy) << 16) | __bfloat16_as_ushort(hx);
    hu.y = ((uint32_t)__bfloat16_as_ushort(hw) << 16) | __bfloat16_as_ushort(hz);
    __nv_bfloat16 lx = __float2bfloat16(v.x - __bfloat162float(hx));
    __nv_bfloat16 ly = __float2bfloat16(v.y - __bfloat162float(hy));
    __nv_bfloat16 lz = __float2bfloat16(v.z - __bfloat162float(hz));
    __nv_bfloat16 lw = __float2bfloat16(v.w - __bfloat162float(hw));
    lu.x = ((uint32_t)__bfloat16_as_ushort(ly) << 16) | __bfloat16_as_ushort(lx);
    lu.y = ((uint32_t)__bfloat16_as_ushort(lw) << 16) | __bfloat16_as_ushort(lz);
}

#define DYN_SMEM 65536

// ---------------- weight prep: transpose + bf16 hi/lo split ----------------
struct WList { const float* w[8]; };
__global__ void prep_w(WList wl) {
    int m = blockIdx.x, n = threadIdx.x;
    const float* W = wl.w[m];
    __nv_bfloat16* oh = g_WTh + m * 16384 + n * 128;
    __nv_bfloat16* ol = g_WTl + m * 16384 + n * 128;
    for (int k = 0; k < 128; k++) {
        float v = W[k * 128 + n];
        __nv_bfloat16 h = __float2bfloat16(v);
        oh[k] = h;
        ol[k] = __float2bfloat16(v - __bfloat162float(h));
    }
}

// ---------------- WA[t][k][h] = sum_dh Wdst[t][k][h*32+dh]*attn[t][h*32+dh] ----------------
__global__ void prep_wa(const float* __restrict__ Wdst, const float* __restrict__ bdst,
                        const float* __restrict__ attn) {
    int t = blockIdx.x, k = threadIdx.x;
    const float* W = Wdst + t * 16384;
    const float* at = attn + t * 128;
    float4 o;
    float* po = &o.x;
#pragma unroll
    for (int h = 0; h < 4; h++) {
        float s = 0.f;
        for (int dh = 0; dh < 32; dh++) s = fmaf(W[k * 128 + h * 32 + dh], at[h * 32 + dh], s);
        po[h] = s;
    }
    ((float4*)(g_WA + t * 512))[k] = o;
    if (k < 4) {
        const float* b = bdst + t * 128;
        float s = 0.f;
        for (int dh = 0; dh < 32; dh++) s = fmaf(b[k * 32 + dh], at[k * 32 + dh], s);
        g_BA[t * 4 + k] = s;
    }
}

// ---------------- categorical gate table + attn-folded copy ----------------
__global__ void gtabk(const float* __restrict__ te, const float* __restrict__ se,
                      const float* __restrict__ Wg, const float* __restrict__ bg,
                      const float* __restrict__ attn0) {
    int c = threadIdx.x, r = blockIdx.x;
    int a = r >> 3, b = r & 7;
    float s = bg[c];
#pragma unroll 8
    for (int j = 0; j < 32; j++) s = fmaf(te[a * 32 + j], Wg[j * 128 + c], s);
#pragma unroll 8
    for (int j = 0; j < 32; j++) s = fmaf(se[b * 32 + j], Wg[(32 + j) * 128 + c], s);
    float g = 1.f / (1.f + expf(-s));
    g_GTAB[r * 128 + c] = g;
    g_GTA0[r * 128 + c] = g * attn0[c];
}

// ---------------- batched wmma GEMM: Y[N,128] = X[N,128] @ W^T-stored + b ----------------
// bf16 hi/lo 3-pass: Ah*Bh + Al*Bh + Ah*Bl, fp32 accumulate.
struct Seg { const float* X; const __nv_bfloat16* Bh; const __nv_bfloat16* Bl;
             const float* bias; float* Y; int nrows; int tofs; };
struct Segs { Seg s[4]; int nseg; };

__global__ void __launch_bounds__(256, 1) mm_gemm(Segs P) {
    extern __shared__ char sm[];
    __nv_bfloat16* Ah = (__nv_bfloat16*)sm;          // 128x128 bf16 (32KB)
    __nv_bfloat16* Al = Ah + 16384;                  // 32KB
    float* Cs = (float*)sm;                          // reuse as 128x128 fp32 staging
    int b = blockIdx.x, si = 0;
    while (si + 1 < P.nseg && b >= P.s[si + 1].tofs) si++;
    Seg sg = P.s[si];
    int r0 = (b - sg.tofs) * 128;
    int tid = threadIdx.x;
    // load + split A
#pragma unroll 4
    for (int i = 0; i < 16; i++) {
        int idx = tid + 256 * i;               // 0..4095 float4s
        int row = idx >> 5, c4 = idx & 31, gr = r0 + row;
        float4 v = (gr < sg.nrows) ? ((const float4*)sg.X)[(size_t)gr * 32 + c4]
                                   : make_float4(0.f, 0.f, 0.f, 0.f);
        uint2 hu, lu;
        split_pack(v, hu, lu);
        *(uint2*)(Ah + row * 128 + c4 * 4) = hu;
        *(uint2*)(Al + row * 128 + c4 * 4) = lu;
    }
    __syncthreads();
    int wid = tid >> 5;
    int wr = (wid >> 1) * 32;   // warp row
    int wc = (wid & 1) * 64;    // warp col
    wmma::fragment<wmma::accumulator, 16, 16, 16, float> acc[2][4];
#pragma unroll
    for (int i = 0; i < 2; i++)
#pragma unroll
        for (int j = 0; j < 4; j++) wmma::fill_fragment(acc[i][j], 0.f);
#pragma unroll
    for (int kk = 0; kk < 8; kk++) {
        wmma::fragment<wmma::matrix_a, 16, 16, 16, __nv_bfloat16, wmma::row_major> ah[2], al[2];
#pragma unroll
        for (int i = 0; i < 2; i++) {
            wmma::load_matrix_sync(ah[i], Ah + (wr + i * 16) * 128 + kk * 16, 128);
            wmma::load_matrix_sync(al[i], Al + (wr + i * 16) * 128 + kk * 16, 128);
        }
#pragma unroll
        for (int j = 0; j < 4; j++) {
            wmma::fragment<wmma::matrix_b, 16, 16, 16, __nv_bfloat16, wmma::col_major> bh, bl;
            wmma::load_matrix_sync(bh, sg.Bh + (wc + j * 16) * 128 + kk * 16, 128);
            wmma::load_matrix_sync(bl, sg.Bl + (wc + j * 16) * 128 + kk * 16, 128);
#pragma unroll
            for (int i = 0; i < 2; i++) {
                wmma::mma_sync(acc[i][j], ah[i], bh, acc[i][j]);
                wmma::mma_sync(acc[i][j], al[i], bh, acc[i][j]);
                wmma::mma_sync(acc[i][j], ah[i], bl, acc[i][j]);
            }
        }
    }
    __syncthreads();
#pragma unroll
    for (int i = 0; i < 2; i++)
#pragma unroll
        for (int j = 0; j < 4; j++)
            wmma::store_matrix_sync(Cs + (wr + i * 16) * 128 + wc + j * 16,
                                    acc[i][j], 128, wmma::mem_row_major);
    __syncthreads();
#pragma unroll 4
    for (int i = 0; i < 16; i++) {
        int idx = tid + 256 * i;
        int row = idx >> 5, c4 = idx & 31, gr = r0 + row;
        if (gr < sg.nrows) {
            float4 v = ((float4*)Cs)[idx];
            float4 bb = ((const float4*)sg.bias)[c4];
            v.x += bb.x; v.y += bb.y; v.z += bb.z; v.w += bb.w;
            ((float4*)sg.Y)[(size_t)gr * 32 + c4] = v;
        }
    }
}

// ---------------- wmma gate GEMM: G2 = sigmoid(gelu(cp@W1+b1) @ W2 + b2) ----------------
__global__ void __launch_bounds__(256, 1) mm_gate(
    const float* __restrict__ cp, const float* __restrict__ W1, const float* __restrict__ b1,
    const __nv_bfloat16* __restrict__ W2h, const __nv_bfloat16* __restrict__ W2l,
    const float* __restrict__ b2, float* __restrict__ G, int E)
{
    extern __shared__ char sm[];
    __nv_bfloat16* Ah = (__nv_bfloat16*)sm;
    __nv_bfloat16* Al = Ah + 16384;
    float* Cs = (float*)sm;
    int r0 = blockIdx.x * 128;
    int tid = threadIdx.x;
#pragma unroll 4
    for (int i = 0; i < 16; i++) {
        int idx = tid + 256 * i;
        int row = idx >> 5, c4 = idx & 31, ge = r0 + row;
        float4 h4 = make_float4(0.f, 0.f, 0.f, 0.f);
        if (ge < E) {
            float x0 = cp[ge * 3 + 0], x1 = cp[ge * 3 + 1], x2 = cp[ge * 3 + 2];
            float4 w0 = ((const float4*)W1)[c4];
            float4 w1 = ((const float4*)(W1 + 128))[c4];
            float4 w2 = ((const float4*)(W1 + 256))[c4];
            float4 bb = ((const float4*)b1)[c4];
            h4.x = fmaf(x0, w0.x, fmaf(x1, w1.x, fmaf(x2, w2.x, bb.x)));
            h4.y = fmaf(x0, w0.y, fmaf(x1, w1.y, fmaf(x2, w2.y, bb.y)));
            h4.z = fmaf(x0, w0.z, fmaf(x1, w1.z, fmaf(x2, w2.z, bb.z)));
            h4.w = fmaf(x0, w0.w, fmaf(x1, w1.w, fmaf(x2, w2.w, bb.w)));
            h4.x = 0.5f * h4.x * (1.f + erff(h4.x * 0.70710678118654752f));
            h4.y = 0.5f * h4.y * (1.f + erff(h4.y * 0.70710678118654752f));
            h4.z = 0.5f * h4.z * (1.f + erff(h4.z * 0.70710678118654752f));
            h4.w = 0.5f * h4.w * (1.f + erff(h4.w * 0.70710678118654752f));
        }
        uint2 hu, lu;
        split_pack(h4, hu, lu);
        *(uint2*)(Ah + row * 128 + c4 * 4) = hu;
        *(uint2*)(Al + row * 128 + c4 * 4) = lu;
    }
    __syncthreads();
    int wid = tid >> 5;
    int wr = (wid >> 1) * 32, wc = (wid & 1) * 64;
    wmma::fragment<wmma::accumulator, 16, 16, 16, float> acc[2][4];
#pragma unroll
    for (int i = 0; i < 2; i++)
#pragma unroll
        for (int j = 0; j < 4; j++) wmma::fill_fragment(acc[i][j], 0.f);
#pragma unroll
    for (int kk = 0; kk < 8; kk++) {
        wmma::fragment<wmma::matrix_a, 16, 16, 16, __nv_bfloat16, wmma::row_major> ah[2], al[2];
#pragma unroll
        for (int i = 0; i < 2; i++) {
            wmma::load_matrix_sync(ah[i], Ah + (wr + i * 16) * 128 + kk * 16, 128);
            wmma::load_matrix_sync(al[i], Al + (wr + i * 16) * 128 + kk * 16, 128);
        }
#pragma unroll
        for (int j = 0; j < 4; j++) {
            wmma::fragment<wmma::matrix_b, 16, 16, 16, __nv_bfloat16, wmma::col_major> bh, bl;
            wmma::load_matrix_sync(bh, W2h + (wc + j * 16) * 128 + kk * 16, 128);
            wmma::load_matrix_sync(bl, W2l + (wc + j * 16) * 128 + kk * 16, 128);
#pragma unroll
            for (int i = 0; i < 2; i++) {
                wmma::mma_sync(acc[i][j], ah[i], bh, acc[i][j]);
                wmma::mma_sync(acc[i][j], al[i], bh, acc[i][j]);
                wmma::mma_sync(acc[i][j], ah[i], bl, acc[i][j]);
            }
        }
    }
    __syncthreads();
#pragma unroll
    for (int i = 0; i < 2; i++)
#pragma unroll
        for (int j = 0; j < 4; j++)
            wmma::store_matrix_sync(Cs + (wr + i * 16) * 128 + wc + j * 16,
                                    acc[i][j], 128, wmma::mem_row_major);
    __syncthreads();
#pragma unroll 4
    for (int i = 0; i < 16; i++) {
        int idx = tid + 256 * i;
        int row = idx >> 5, c4 = idx & 31, ge = r0 + row;
        if (ge < E) {
            float4 v = ((float4*)Cs)[idx];
            float4 bb = ((const float4*)b2)[c4];
            float4 o;
            o.x = 1.f / (1.f + expf(-(v.x + bb.x)));
            o.y = 1.f / (1.f + expf(-(v.y + bb.y)));
            o.z = 1.f / (1.f + expf(-(v.z + bb.z)));
            o.w = 1.f / (1.f + expf(-(v.w + bb.w)));
            ((float4*)G)[(size_t)ge * 32 + c4] = o;
        }
    }
}

// ---------------- AD[n,h] = x[n] @ WA_t + BA_t (warp per row) ----------------
__global__ void adK(const float* __restrict__ x, const float* __restrict__ WA,
                    const float* __restrict__ BA, float* __restrict__ AD, int n)
{
    int r = (int)((blockIdx.x * (size_t)blockDim.x + threadIdx.x) >> 5);
    if (r >= n) return;
    int lane = threadIdx.x & 31;
    float4 xv = ((const float4*)(x + (size_t)r * 128))[lane];
    const float4* W4 = (const float4*)WA;
    float4 a0 = W4[4 * lane], a1 = W4[4 * lane + 1], a2 = W4[4 * lane + 2], a3 = W4[4 * lane + 3];
    float p0 = xv.x * a0.x + xv.y * a1.x + xv.z * a2.x + xv.w * a3.x;
    float p1 = xv.x * a0.y + xv.y * a1.y + xv.z * a2.y + xv.w * a3.y;
    float p2 = xv.x * a0.z + xv.y * a1.z + xv.z * a2.z + xv.w * a3.z;
    float p3 = xv.x * a0.w + xv.y * a1.w + xv.z * a2.w + xv.w * a3.w;
#pragma unroll
    for (int m = 16; m; m >>= 1) {
        p0 += __shfl_xor_sync(0xffffffffu, p0, m);
        p1 += __shfl_xor_sync(0xffffffffu, p1, m);
        p2 += __shfl_xor_sync(0xffffffffu, p2, m);
        p3 += __shfl_xor_sync(0xffffffffu, p3, m);
    }
    if (lane == 0)
        ((float4*)AD)[r] = make_float4(p0 + BA[0], p1 + BA[1], p2 + BA[2], p3 + BA[3]);
}

// ---------------- AS[n,h] = sum_dh HS[n,h*32+dh]*attn[h*32+dh] ----------------
__global__ void asK(const float* __restrict__ HS, const float* __restrict__ at,
                    float* __restrict__ AS, int n)
{
    int r = (int)((blockIdx.x * (size_t)blockDim.x + threadIdx.x) >> 5);
    if (r >= n) return;
    int lane = threadIdx.x & 31;
    float4 h = ((const float4*)(HS + (size_t)r * 128))[lane];
    float4 a = ((const float4*)at)[lane];
    float p = h.x * a.x + h.y * a.y + h.z * a.z + h.w * a.w;
    p += __shfl_xor_sync(0xffffffffu, p, 4);
    p += __shfl_xor_sync(0xffffffffu, p, 2);
    p += __shfl_xor_sync(0xffffffffu, p, 1);
    if ((lane & 7) == 0) AS[r * 4 + (lane >> 3)] = p;
}

// ---------------- P2 = HS2 * attn2 (pointwise) ----------------
__global__ void p2K(const float* __restrict__ HS2, const float* __restrict__ at,
                    float* __restrict__ P2, int n4)
{
    int i = blockIdx.x * blockDim.x + threadIdx.x;
    if (i >= n4) return;
    float4 h = ((const float4*)HS2)[i];
    float4 a = ((const float4*)at)[i & 31];
    ((float4*)P2)[i] = make_float4(h.x * a.x, h.y * a.y, h.z * a.z, h.w * a.w);
}

// ---------------- passA t0: warp/edge, gated by GTA0 (attn folded) ----------------
__global__ void __launch_bounds__(256) passA0(
    const float* __restrict__ HS, const int* __restrict__ src, const int* __restrict__ dst,
    const int* __restrict__ cg, const float* __restrict__ AD,
    float* __restrict__ expv, float* __restrict__ seg, int E)
{
    int e = (int)((blockIdx.x * (size_t)blockDim.x + threadIdx.x) >> 5);
    if (e >= E) return;
    int lane = threadIdx.x & 31;
    int s = src[e], d = dst[e];
    float4 hs = ((const float4*)(HS + (size_t)s * 128))[lane];
    int a = cg[2 * e], b = cg[2 * e + 1];
    float4 g = ((const float4*)(g_GTA0 + (a * 8 + b) * 128))[lane];
    float p = hs.x * g.x + hs.y * g.y + hs.z * g.z + hs.w * g.w;
    p += __shfl_xor_sync(0xffffffffu, p, 4);
    p += __shfl_xor_sync(0xffffffffu, p, 2);
    p += __shfl_xor_sync(0xffffffffu, p, 1);
    float h0 = __shfl_sync(0xffffffffu, p, 0);
    float h1 = __shfl_sync(0xffffffffu, p, 8);
    float h2 = __shfl_sync(0xffffffffu, p, 16);
    float h3 = __shfl_sync(0xffffffffu, p, 24);
    if (lane == 0) {
        float4 ad = ((const float4*)AD)[d];
        float l0 = h0 + ad.x, l1 = h1 + ad.y, l2 = h2 + ad.z, l3 = h3 + ad.w;
        float4 ex;
        ex.x = expf(l0 > 0.f ? l0 : 0.2f * l0);
        ex.y = expf(l1 > 0.f ? l1 : 0.2f * l1);
        ex.z = expf(l2 > 0.f ? l2 : 0.2f * l2);
        ex.w = expf(l3 > 0.f ? l3 : 0.2f * l3);
        ((float4*)expv)[e] = ex;
        red_add_v4(seg + (size_t)d * 4, ex);
    }
}

// ---------------- passA t2: warp/edge, P2 . G2 ----------------
__global__ void __launch_bounds__(256) passA2(
    const float* __restrict__ P2, const int* __restrict__ src, const int* __restrict__ dst,
    const float* __restrict__ G2, const float* __restrict__ AD,
    float* __restrict__ expv, float* __restrict__ seg, int E)
{
    int e = (int)((blockIdx.x * (size_t)blockDim.x + threadIdx.x) >> 5);
    if (e >= E) return;
    int lane = threadIdx.x & 31;
    int s = src[e], d = dst[e];
    float4 hs = ((const float4*)(P2 + (size_t)s * 128))[lane];
    float4 g = ((const float4*)(G2 + (size_t)e * 128))[lane];
    float p = hs.x * g.x + hs.y * g.y + hs.z * g.z + hs.w * g.w;
    p += __shfl_xor_sync(0xffffffffu, p, 4);
    p += __shfl_xor_sync(0xffffffffu, p, 2);
    p += __shfl_xor_sync(0xffffffffu, p, 1);
    float h0 = __shfl_sync(0xffffffffu, p, 0);
    float h1 = __shfl_sync(0xffffffffu, p, 8);
    float h2 = __shfl_sync(0xffffffffu, p, 16);
    float h3 = __shfl_sync(0xffffffffu, p, 24);
    if (lane == 0) {
        float4 ad = ((const float4*)AD)[d];
        float l0 = h0 + ad.x, l1 = h1 + ad.y, l2 = h2 + ad.z, l3 = h3 + ad.w;
        float4 ex;
        ex.x = expf(l0 > 0.f ? l0 : 0.2f * l0);
        ex.y = expf(l1 > 0.f ? l1 : 0.2f * l1);
        ex.z = expf(l2 > 0.f ? l2 : 0.2f * l2);
        ex.w = expf(l3 > 0.f ? l3 : 0.2f * l3);
        ((float4*)expv)[e] = ex;
        red_add_v4(seg + (size_t)d * 4, ex);
    }
}

// ---------------- passA t1/t3: thread/edge via AS/AD ----------------
__global__ void __launch_bounds__(256) passAL(
    const float* __restrict__ AS, const int* __restrict__ src, const int* __restrict__ dst,
    const float* __restrict__ AD, float* __restrict__ expv, float* __restrict__ seg, int E)
{
    int e = blockIdx.x * blockDim.x + threadIdx.x;
    if (e >= E) return;
    float4 as = ((const float4*)AS)[src[e]];
    int d = dst[e];
    float4 ad = ((const float4*)AD)[d];
    float l0 = as.x + ad.x, l1 = as.y + ad.y, l2 = as.z + ad.z, l3 = as.w + ad.w;
    float4 ex;
    ex.x = expf(l0 > 0.f ? l0 : 0.2f * l0);
    ex.y = expf(l1 > 0.f ? l1 : 0.2f * l1);
    ex.z = expf(l2 > 0.f ? l2 : 0.2f * l2);
    ex.w = expf(l3 > 0.f ? l3 : 0.2f * l3);
    ((float4*)expv)[e] = ex;
    red_add_v4(seg + (size_t)d * 4, ex);
}

// ---------------- passB: alpha * gated_ms scattered into acc ----------------
__global__ void __launch_bounds__(256) passB(
    const float* __restrict__ HS,
    const int* __restrict__ src, const int* __restrict__ dst,
    const float* __restrict__ gate, const int* __restrict__ cg,
    const float* __restrict__ expv, const float* __restrict__ segsum,
    float* __restrict__ acc, int E)
{
    int e = (int)((blockIdx.x * (size_t)blockDim.x + threadIdx.x) >> 5);
    if (e >= E) return;
    int lane = threadIdx.x & 31;
    int s = src[e], d = dst[e];
    int h = lane >> 3;
    float al = expv[4 * e + h] / segsum[(size_t)d * 4 + h];
    float4 ms = ((const float4*)(HS + (size_t)s * 128))[lane];
    if (gate) {
        float4 g = ((const float4*)(gate + (size_t)e * 128))[lane];
        ms.x *= g.x; ms.y *= g.y; ms.z *= g.z; ms.w *= g.w;
    } else if (cg) {
        int a = cg[2 * e], b = cg[2 * e + 1];
        float4 g = ((const float4*)(g_GTAB + (a * 8 + b) * 128))[lane];
        ms.x *= g.x; ms.y *= g.y; ms.z *= g.z; ms.w *= g.w;
    }
    float4 o = make_float4(al * ms.x, al * ms.y, al * ms.z, al * ms.w);
    red_add_v4(acc + (size_t)d * 128 + lane * 4, o);
}

__global__ void biasfill(float* __restrict__ out, const float* __restrict__ b, int n)
{
    int i = blockIdx.x * blockDim.x + threadIdx.x;
    if (i < n * 128) out[i] = b[i & 127];
}

// ---------------- launch ----------------
extern "C" void kernel_launch(void* const* d_in, const int* in_sizes, int n_in,
                              void* d_out, int out_size)
{
    int iWsrc, ibsrc, iWdst, ibdst, iattn, itemb, isemb, iWg, ibg, iW1c, ib1c,
        iW2c, ib2c, iWout, ibout, icp, icg;
    int isrc[4], idst[4];
    if (in_sizes[4] == 65536) {            // layout A: Wsrc at slot 4
        iWsrc = 4; ibsrc = 5; iWdst = 6; ibdst = 7; iattn = 8; itemb = 9; isemb = 10;
        iWg = 11; ibg = 12; iW1c = 13; ib1c = 14; iW2c = 15; ib2c = 16;
        iWout = 17; ibout = 18; icp = 19;
        isrc[0] = 20; idst[0] = 21; isrc[1] = 22; idst[1] = 23;
        isrc[2] = 24; idst[2] = 25; isrc[3] = 26; idst[3] = 27; icg = 28;
    } else {                               // layout B: src0 at slot 4
        isrc[0] = 4; idst[0] = 5; isrc[1] = 6; idst[1] = 7;
        isrc[2] = 8; idst[2] = 9; isrc[3] = 10; idst[3] = 11;
        icg = 12; icp = 13;
        iWsrc = 14; ibsrc = 15; iWdst = 16; ibdst = 17; iattn = 18;
        itemb = 19; isemb = 20; iWg = 21; ibg = 22; iW1c = 23; ib1c = 24;
        iW2c = 25; ib2c = 26; iWout = 27; ibout = 28;
    }

    const float* x[4]  = {(const float*)d_in[0], (const float*)d_in[1],
                          (const float*)d_in[2], (const float*)d_in[3]};
    const float* Wsrc  = (const float*)d_in[iWsrc];
    const float* bsrc  = (const float*)d_in[ibsrc];
    const float* Wdst  = (const float*)d_in[iWdst];
    const float* bdst  = (const float*)d_in[ibdst];
    const float* attn  = (const float*)d_in[iattn];
    const float* temb  = (const float*)d_in[itemb];
    const float* semb  = (const float*)d_in[isemb];
    const float* Wg    = (const float*)d_in[iWg];
    const float* bg    = (const float*)d_in[ibg];
    const float* W1c   = (const float*)d_in[iW1c];
    const float* b1c   = (const float*)d_in[ib1c];
    const float* W2c   = (const float*)d_in[iW2c];
    const float* b2c   = (const float*)d_in[ib2c];
    const float* Wout  = (const float*)d_in[iWout];
    const float* bout  = (const float*)d_in[ibout];
    const float* cp    = (const float*)d_in[icp];
    const int* srcp[4] = {(const int*)d_in[isrc[0]], (const int*)d_in[isrc[1]],
                          (const int*)d_in[isrc[2]], (const int*)d_in[isrc[3]]};
    const int* dstp[4] = {(const int*)d_in[idst[0]], (const int*)d_in[idst[1]],
                          (const int*)d_in[idst[2]], (const int*)d_in[idst[3]]};
    const int* cg      = (const int*)d_in[icg];
    float* out = (float*)d_out;

    int Nn[4] = {in_sizes[0] / 128, in_sizes[1] / 128, in_sizes[2] / 128, in_sizes[3] / 128};
    int Ee[4] = {in_sizes[isrc[0]], in_sizes[isrc[1]], in_sizes[isrc[2]], in_sizes[isrc[3]]};
    int sidx[4] = {0, 1, 0, 2};
    int didx[4] = {1, 0, 3, 1};

    float *H, *G2, *P2, *EXPV, *SEG, *ACC, *AS, *AD, *WA, *BA;
    __nv_bfloat16 *WTh, *WTl;
    cudaGetSymbolAddress((void**)&H, g_H);
    cudaGetSymbolAddress((void**)&G2, g_G2);
    cudaGetSymbolAddress((void**)&P2, g_P2);
    cudaGetSymbolAddress((void**)&EXPV, g_EXPV);
    cudaGetSymbolAddress((void**)&SEG, g_SEG);
    cudaGetSymbolAddress((void**)&ACC, g_ACC);
    cudaGetSymbolAddress((void**)&AS, g_AS);
    cudaGetSymbolAddress((void**)&AD, g_AD);
    cudaGetSymbolAddress((void**)&WA, g_WA);
    cudaGetSymbolAddress((void**)&BA, g_BA);
    cudaGetSymbolAddress((void**)&WTh, g_WTh);
    cudaGetSymbolAddress((void**)&WTl, g_WTl);

    cudaFuncSetAttribute(mm_gemm, cudaFuncAttributeMaxDynamicSharedMemorySize, DYN_SMEM);
    cudaFuncSetAttribute(mm_gate, cudaFuncAttributeMaxDynamicSharedMemorySize, DYN_SMEM);

    size_t hofs[4] = {0, 50000, 80000, 130000};
    float* HSp[4] = {H, H + hofs[1] * 128, H + hofs[2] * 128, H + hofs[3] * 128};
    float* EXP_t[4] = {EXPV, EXPV + 2000000, EXPV + 4000000, EXPV + 5000000};
    float* SEG_t[4] = {SEG, SEG + 200000, SEG + 400000, SEG + 600000};
    float* AD_t[4]  = {AD, AD + 200000, AD + 400000, AD + 600000};
    float* accp[4];
    accp[0] = ACC;
    accp[1] = ACC + (size_t)Nn[0] * 128;
    accp[2] = nullptr;
    accp[3] = ACC + (size_t)(Nn[0] + Nn[1]) * 128;
    float* accd[4] = {accp[1], accp[0], accp[3], accp[1]};

    // 1. weight prep
    WList wl;
    wl.w[0] = Wsrc;             wl.w[1] = Wsrc + 16384;
    wl.w[2] = Wsrc + 2 * 16384; wl.w[3] = Wsrc + 3 * 16384;
    wl.w[4] = Wout;             wl.w[5] = Wout + 16384;
    wl.w[6] = Wout + 3 * 16384; wl.w[7] = W2c;
    prep_w<<<8, 128>>>(wl);
    prep_wa<<<4, 128>>>(Wdst, bdst, attn);
    gtabk<<<80, 128>>>(temb, semb, Wg, bg, attn);

    // 2. source transforms (batched wmma GEMM)
    Segs T;
    T.nseg = 4;
    int tcum = 0;
    for (int t = 0; t < 4; t++) {
        int ns = Nn[sidx[t]];
        T.s[t].X = x[sidx[t]];
        T.s[t].Bh = WTh + t * 16384;
        T.s[t].Bl = WTl + t * 16384;
        T.s[t].bias = bsrc + t * 128;
        T.s[t].Y = HSp[t];
        T.s[t].nrows = ns;
        T.s[t].tofs = tcum;
        tcum += (ns + 127) / 128;
    }
    mm_gemm<<<tcum, 256, DYN_SMEM>>>(T);

    // 3. continuous gate
    mm_gate<<<(Ee[2] + 127) / 128, 256, DYN_SMEM>>>(cp, W1c, b1c,
        WTh + 7 * 16384, WTl + 7 * 16384, b2c, G2, Ee[2]);

    // 4. attn precomputes
    p2K<<<(Nn[0] * 32 + 255) / 256, 256>>>(HSp[2], attn + 2 * 128, P2, Nn[0] * 32);
    asK<<<(Nn[1] * 32 + 255) / 256, 256>>>(HSp[1], attn + 1 * 128, AS, Nn[1]);
    asK<<<(Nn[2] * 32 + 255) / 256, 256>>>(HSp[3], attn + 3 * 128, AS + 200000, Nn[2]);
    for (int t = 0; t < 4; t++) {
        int nd = Nn[didx[t]];
        adK<<<(nd * 32 + 255) / 256, 256>>>(x[didx[t]], WA + t * 512, BA + t * 4, AD_t[t], nd);
    }

    // 5. zero segment sums + accumulators
    cudaMemsetAsync(SEG, 0, 4 * 200000 * sizeof(float));
    cudaMemsetAsync(ACC, 0, (size_t)(Nn[0] + Nn[1] + Nn[3]) * 128 * sizeof(float));

    // 6. passA
    passA0<<<(Ee[0] + 7) / 8, 256>>>(HSp[0], srcp[0], dstp[0], cg, AD_t[0],
                                     EXP_t[0], SEG_t[0], Ee[0]);
    passAL<<<(Ee[1] + 255) / 256, 256>>>(AS, srcp[1], dstp[1], AD_t[1],
                                         EXP_t[1], SEG_t[1], Ee[1]);
    passA2<<<(Ee[2] + 7) / 8, 256>>>(P2, srcp[2], dstp[2], G2, AD_t[2],
                                     EXP_t[2], SEG_t[2], Ee[2]);
    passAL<<<(Ee[3] + 255) / 256, 256>>>(AS + 200000, srcp[3], dstp[3], AD_t[3],
                                         EXP_t[3], SEG_t[3], Ee[3]);

    // 7. passB
    for (int t = 0; t < 4; t++) {
        const float* gate = (t == 2) ? G2 : nullptr;
        const int* cgp = (t == 0) ? cg : nullptr;
        passB<<<(Ee[t] + 7) / 8, 256>>>(HSp[t], srcp[t], dstp[t], gate, cgp,
                                        EXP_t[t], SEG_t[t], accd[t], Ee[t]);
    }

    // 8. output GEMMs
    float* o_chem = out;
    float* o_gene = o_chem + (size_t)Nn[0] * 128;
    float* o_dis  = o_gene + (size_t)Nn[1] * 128;
    float* o_path = o_dis + (size_t)Nn[2] * 128;
    Segs O;
    O.nseg = 3;
    O.s[0] = {accp[0], WTh + 4 * 16384, WTl + 4 * 16384, bout,       o_chem, Nn[0], 0};
    int t1 = (Nn[0] + 127) / 128;
    O.s[1] = {accp[1], WTh + 5 * 16384, WTl + 5 * 16384, bout + 128, o_gene, Nn[1], t1};
    int t2 = t1 + (Nn[1] + 127) / 128;
    O.s[2] = {accp[3], WTh + 6 * 16384, WTl + 6 * 16384, bout + 384, o_path, Nn[3], t2};
    int t3 = t2 + (Nn[3] + 127) / 128;
    mm_gemm<<<t3, 256, DYN_SMEM>>>(O);
    biasfill<<<(Nn[2] * 128 + 255) / 256, 256>>>(o_dis, bout + 256, Nn[2]);
}

// round 6
// speedup vs baseline: 1.3086x; 1.3064x over previous
#include <cuda_runtime.h>
#include <cuda_bf16.h>
#include <mma.h>
#include <math.h>
#include <stdint.h>

using namespace nvcuda;

// ---------------- static scratch ----------------
__device__ float g_H[140000 * 128];     // HS tables: t0@0(50k) t1@50k(30k) t2@80k(50k) t3@130k(10k)
__device__ float g_G2[250000 * 128];    // per-edge continuous gate (t2)
__device__ float g_P2[50000 * 128];     // HS2 * attn2 (pointwise)
__device__ float g_EXPV[1500000 * 4];   // per-edge exp(logit) per head (all 4 types)
__device__ float g_SEG[4 * 50000 * 4];  // per-(type,dst) softmax denominators
__device__ float g_ACC[85000 * 128];    // chem[0,50k) gene[50k,80k) path[80k,85k)
__device__ float g_GTAB[80 * 128];      // categorical gate table
__device__ float g_GTA0[80 * 128];      // gate table * attn0
__device__ float g_AS[2 * 50000 * 4];   // per-src attn dots (t1 @0, t3 @200000)
__device__ float g_AD[4 * 50000 * 4];   // per-dst attn dots, per edge type
__device__ float g_WA[4 * 128 * 4];     // Wdst collapsed with attn
__device__ float g_BA[4 * 4];
__device__ __nv_bfloat16 g_WTh[8 * 16384]; // weights [k][n] row-major, bf16 hi
__device__ __nv_bfloat16 g_WTl[8 * 16384]; // weights [k][n] row-major, bf16 lo

__device__ __forceinline__ void red_add_v4(float* p, float4 v) {
    asm volatile("red.global.add.v4.f32 [%0], {%1,%2,%3,%4};"
                 :: "l"(p), "f"(v.x), "f"(v.y), "f"(v.z), "f"(v.w) : "memory");
}

__device__ __forceinline__ void split_pack(float4 v, uint2& hu, uint2& lu) {
    __nv_bfloat16 hx = __float2bfloat16(v.x), hy = __float2bfloat16(v.y);
    __nv_bfloat16 hz = __float2bfloat16(v.z), hw = __float2bfloat16(v.w);
    hu.x = ((uint32_t)__bfloat16_as_ushort(hy) << 16) | __bfloat16_as_ushort(hx);
    hu.y = ((uint32_t)__bfloat16_as_ushort(hw) << 16) | __bfloat16_as_ushort(hz);
    __nv_bfloat16 lx = __float2bfloat16(v.x - __bfloat162float(hx));
    __nv_bfloat16 ly = __float2bfloat16(v.y - __bfloat162float(hy));
    __nv_bfloat16 lz = __float2bfloat16(v.z - __bfloat162float(hz));
    __nv_bfloat16 lw = __float2bfloat16(v.w - __bfloat162float(hw));
    lu.x = ((uint32_t)__bfloat16_as_ushort(ly) << 16) | __bfloat16_as_ushort(lx);
    lu.y = ((uint32_t)__bfloat16_as_ushort(lw) << 16) | __bfloat16_as_ushort(lz);
}

#define LDM 136                         // padded smem leading dim (bf16 elems)
#define DYN_SMEM (4 * 128 * LDM * 2)    // Ah, Al, Bh, Bl = 139264 B

// ---------------- weight prep: elementwise bf16 hi/lo split (no transpose) ----------------
struct WList { const float* w[8]; };
__global__ void prep_w(WList wl) {
    int m = blockIdx.x;
    int idx = blockIdx.y * 256 + threadIdx.x;   // 0..16383
    float v = wl.w[m][idx];
    __nv_bfloat16 h = __float2bfloat16(v);
    g_WTh[m * 16384 + idx] = h;
    g_WTl[m * 16384 + idx] = __float2bfloat16(v - __bfloat162float(h));
}

// ---------------- WA[t][k][h] = sum_dh Wdst[t][k][h*32+dh]*attn[t][h*32+dh] ----------------
__global__ void prep_wa(const float* __restrict__ Wdst, const float* __restrict__ bdst,
                        const float* __restrict__ attn) {
    int t = blockIdx.x, k = threadIdx.x;
    const float* W = Wdst + t * 16384;
    const float* at = attn + t * 128;
    float4 o;
    float* po = &o.x;
#pragma unroll
    for (int h = 0; h < 4; h++) {
        float s = 0.f;
        for (int dh = 0; dh < 32; dh++) s = fmaf(W[k * 128 + h * 32 + dh], at[h * 32 + dh], s);
        po[h] = s;
    }
    ((float4*)(g_WA + t * 512))[k] = o;
    if (k < 4) {
        const float* b = bdst + t * 128;
        float s = 0.f;
        for (int dh = 0; dh < 32; dh++) s = fmaf(b[k * 32 + dh], at[k * 32 + dh], s);
        g_BA[t * 4 + k] = s;
    }
}

// ---------------- categorical gate table + attn-folded copy ----------------
__global__ void gtabk(const float* __restrict__ te, const float* __restrict__ se,
                      const float* __restrict__ Wg, const float* __restrict__ bg,
                      const float* __restrict__ attn0) {
    int c = threadIdx.x, r = blockIdx.x;
    int a = r >> 3, b = r & 7;
    float s = bg[c];
#pragma unroll 8
    for (int j = 0; j < 32; j++) s = fmaf(te[a * 32 + j], Wg[j * 128 + c], s);
#pragma unroll 8
    for (int j = 0; j < 32; j++) s = fmaf(se[b * 32 + j], Wg[(32 + j) * 128 + c], s);
    float g = 1.f / (1.f + expf(-s));
    g_GTAB[r * 128 + c] = g;
    g_GTA0[r * 128 + c] = g * attn0[c];
}

// ---------------- shared wmma core: C(smem fp32) = A(hi/lo) @ B(hi/lo), 3-pass ----------------
__device__ __forceinline__ void wmma_core(__nv_bfloat16* Ah, __nv_bfloat16* Al,
                                          __nv_bfloat16* Bh, __nv_bfloat16* Bl,
                                          float* Cs, int wid)
{
    int wr = (wid >> 1) * 32;   // warp rows
    int wc = (wid & 1) * 64;    // warp cols
    wmma::fragment<wmma::accumulator, 16, 16, 16, float> acc[2][4];
#pragma unroll
    for (int i = 0; i < 2; i++)
#pragma unroll
        for (int j = 0; j < 4; j++) wmma::fill_fragment(acc[i][j], 0.f);
#pragma unroll
    for (int kk = 0; kk < 8; kk++) {
        wmma::fragment<wmma::matrix_a, 16, 16, 16, __nv_bfloat16, wmma::row_major> ah[2], al[2];
#pragma unroll
        for (int i = 0; i < 2; i++) {
            wmma::load_matrix_sync(ah[i], Ah + (wr + i * 16) * LDM + kk * 16, LDM);
            wmma::load_matrix_sync(al[i], Al + (wr + i * 16) * LDM + kk * 16, LDM);
        }
#pragma unroll
        for (int j = 0; j < 4; j++) {
            wmma::fragment<wmma::matrix_b, 16, 16, 16, __nv_bfloat16, wmma::row_major> bh, bl;
            wmma::load_matrix_sync(bh, Bh + (kk * 16) * LDM + wc + j * 16, LDM);
            wmma::load_matrix_sync(bl, Bl + (kk * 16) * LDM + wc + j * 16, LDM);
#pragma unroll
            for (int i = 0; i < 2; i++) {
                wmma::mma_sync(acc[i][j], ah[i], bh, acc[i][j]);
                wmma::mma_sync(acc[i][j], al[i], bh, acc[i][j]);
                wmma::mma_sync(acc[i][j], ah[i], bl, acc[i][j]);
            }
        }
    }
    __syncthreads();   // Cs aliases Ah/Al
#pragma unroll
    for (int i = 0; i < 2; i++)
#pragma unroll
        for (int j = 0; j < 4; j++)
            wmma::store_matrix_sync(Cs + (wr + i * 16) * 128 + wc + j * 16,
                                    acc[i][j], 128, wmma::mem_row_major);
}

// copy B (row-major [k][n] bf16 hi/lo, 128x128) into padded smem, coalesced.
// uint4 = 16B = 8 bf16 elems -> 16 uint4 per 128-elem row.
__device__ __forceinline__ void stage_B(const __nv_bfloat16* gBh, const __nv_bfloat16* gBl,
                                        __nv_bfloat16* Bh, __nv_bfloat16* Bl, int tid)
{
    const uint4* bh = (const uint4*)gBh;
    const uint4* bl = (const uint4*)gBl;
#pragma unroll
    for (int i = 0; i < 8; i++) {
        int idx = tid + 256 * i;           // 0..2047 uint4 (16 per row)
        int row = idx >> 4, c = idx & 15;
        *(uint4*)(Bh + row * LDM + c * 8) = bh[idx];
        *(uint4*)(Bl + row * LDM + c * 8) = bl[idx];
    }
}

// ---------------- batched wmma GEMM: Y[N,128] = X[N,128] @ W + b ----------------
struct Seg { const float* X; const __nv_bfloat16* Bh; const __nv_bfloat16* Bl;
             const float* bias; float* Y; int nrows; int tofs; };
struct Segs { Seg s[4]; int nseg; };

__global__ void __launch_bounds__(256, 1) mm_gemm(Segs P) {
    extern __shared__ char sm[];
    __nv_bfloat16* Ah = (__nv_bfloat16*)sm;
    __nv_bfloat16* Al = Ah + 128 * LDM;
    __nv_bfloat16* Bh = Al + 128 * LDM;
    __nv_bfloat16* Bl = Bh + 128 * LDM;
    float* Cs = (float*)sm;                  // reuse A region for output staging
    int b = blockIdx.x, si = 0;
    while (si + 1 < P.nseg && b >= P.s[si + 1].tofs) si++;
    Seg sg = P.s[si];
    int r0 = (b - sg.tofs) * 128;
    int tid = threadIdx.x;
#pragma unroll 4
    for (int i = 0; i < 16; i++) {
        int idx = tid + 256 * i;             // 0..4095 float4s
        int row = idx >> 5, c4 = idx & 31, gr = r0 + row;
        float4 v = (gr < sg.nrows) ? ((const float4*)sg.X)[(size_t)gr * 32 + c4]
                                   : make_float4(0.f, 0.f, 0.f, 0.f);
        uint2 hu, lu;
        split_pack(v, hu, lu);
        *(uint2*)(Ah + row * LDM + c4 * 4) = hu;
        *(uint2*)(Al + row * LDM + c4 * 4) = lu;
    }
    stage_B(sg.Bh, sg.Bl, Bh, Bl, tid);
    __syncthreads();
    wmma_core(Ah, Al, Bh, Bl, Cs, tid >> 5);
    __syncthreads();
#pragma unroll 4
    for (int i = 0; i < 16; i++) {
        int idx = tid + 256 * i;
        int row = idx >> 5, c4 = idx & 31, gr = r0 + row;
        if (gr < sg.nrows) {
            float4 v = ((float4*)Cs)[idx];
            float4 bb = ((const float4*)sg.bias)[c4];
            v.x += bb.x; v.y += bb.y; v.z += bb.z; v.w += bb.w;
            ((float4*)sg.Y)[(size_t)gr * 32 + c4] = v;
        }
    }
}

// ---------------- wmma gate GEMM: G2 = sigmoid(gelu(cp@W1+b1) @ W2 + b2) ----------------
__global__ void __launch_bounds__(256, 1) mm_gate(
    const float* __restrict__ cp, const float* __restrict__ W1, const float* __restrict__ b1,
    const __nv_bfloat16* __restrict__ W2h, const __nv_bfloat16* __restrict__ W2l,
    const float* __restrict__ b2, float* __restrict__ G, int E)
{
    extern __shared__ char sm[];
    __nv_bfloat16* Ah = (__nv_bfloat16*)sm;
    __nv_bfloat16* Al = Ah + 128 * LDM;
    __nv_bfloat16* Bh = Al + 128 * LDM;
    __nv_bfloat16* Bl = Bh + 128 * LDM;
    float* Cs = (float*)sm;
    int r0 = blockIdx.x * 128;
    int tid = threadIdx.x;
#pragma unroll 4
    for (int i = 0; i < 16; i++) {
        int idx = tid + 256 * i;
        int row = idx >> 5, c4 = idx & 31, ge = r0 + row;
        float4 h4 = make_float4(0.f, 0.f, 0.f, 0.f);
        if (ge < E) {
            float x0 = cp[ge * 3 + 0], x1 = cp[ge * 3 + 1], x2 = cp[ge * 3 + 2];
            float4 w0 = ((const float4*)W1)[c4];
            float4 w1 = ((const float4*)(W1 + 128))[c4];
            float4 w2 = ((const float4*)(W1 + 256))[c4];
            float4 bb = ((const float4*)b1)[c4];
            h4.x = fmaf(x0, w0.x, fmaf(x1, w1.x, fmaf(x2, w2.x, bb.x)));
            h4.y = fmaf(x0, w0.y, fmaf(x1, w1.y, fmaf(x2, w2.y, bb.y)));
            h4.z = fmaf(x0, w0.z, fmaf(x1, w1.z, fmaf(x2, w2.z, bb.z)));
            h4.w = fmaf(x0, w0.w, fmaf(x1, w1.w, fmaf(x2, w2.w, bb.w)));
            h4.x = 0.5f * h4.x * (1.f + erff(h4.x * 0.70710678118654752f));
            h4.y = 0.5f * h4.y * (1.f + erff(h4.y * 0.70710678118654752f));
            h4.z = 0.5f * h4.z * (1.f + erff(h4.z * 0.70710678118654752f));
            h4.w = 0.5f * h4.w * (1.f + erff(h4.w * 0.70710678118654752f));
        }
        uint2 hu, lu;
        split_pack(h4, hu, lu);
        *(uint2*)(Ah + row * LDM + c4 * 4) = hu;
        *(uint2*)(Al + row * LDM + c4 * 4) = lu;
    }
    stage_B(W2h, W2l, Bh, Bl, tid);
    __syncthreads();
    wmma_core(Ah, Al, Bh, Bl, Cs, tid >> 5);
    __syncthreads();
#pragma unroll 4
    for (int i = 0; i < 16; i++) {
        int idx = tid + 256 * i;
        int row = idx >> 5, c4 = idx & 31, ge = r0 + row;
        if (ge < E) {
            float4 v = ((float4*)Cs)[idx];
            float4 bb = ((const float4*)b2)[c4];
            float4 o;
            o.x = 1.f / (1.f + expf(-(v.x + bb.x)));
            o.y = 1.f / (1.f + expf(-(v.y + bb.y)));
            o.z = 1.f / (1.f + expf(-(v.z + bb.z)));
            o.w = 1.f / (1.f + expf(-(v.w + bb.w)));
            ((float4*)G)[(size_t)ge * 32 + c4] = o;
        }
    }
}

// ---------------- AD[n,h] = x[n] @ WA_t + BA_t (warp per row) ----------------
__global__ void adK(const float* __restrict__ x, const float* __restrict__ WA,
                    const float* __restrict__ BA, float* __restrict__ AD, int n)
{
    int r = (int)((blockIdx.x * (size_t)blockDim.x + threadIdx.x) >> 5);
    if (r >= n) return;
    int lane = threadIdx.x & 31;
    float4 xv = ((const float4*)(x + (size_t)r * 128))[lane];
    const float4* W4 = (const float4*)WA;
    float4 a0 = W4[4 * lane], a1 = W4[4 * lane + 1], a2 = W4[4 * lane + 2], a3 = W4[4 * lane + 3];
    float p0 = xv.x * a0.x + xv.y * a1.x + xv.z * a2.x + xv.w * a3.x;
    float p1 = xv.x * a0.y + xv.y * a1.y + xv.z * a2.y + xv.w * a3.y;
    float p2 = xv.x * a0.z + xv.y * a1.z + xv.z * a2.z + xv.w * a3.z;
    float p3 = xv.x * a0.w + xv.y * a1.w + xv.z * a2.w + xv.w * a3.w;
#pragma unroll
    for (int m = 16; m; m >>= 1) {
        p0 += __shfl_xor_sync(0xffffffffu, p0, m);
        p1 += __shfl_xor_sync(0xffffffffu, p1, m);
        p2 += __shfl_xor_sync(0xffffffffu, p2, m);
        p3 += __shfl_xor_sync(0xffffffffu, p3, m);
    }
    if (lane == 0)
        ((float4*)AD)[r] = make_float4(p0 + BA[0], p1 + BA[1], p2 + BA[2], p3 + BA[3]);
}

// ---------------- AS[n,h] = sum_dh HS[n,h*32+dh]*attn[h*32+dh] ----------------
__global__ void asK(const float* __restrict__ HS, const float* __restrict__ at,
                    float* __restrict__ AS, int n)
{
    int r = (int)((blockIdx.x * (size_t)blockDim.x + threadIdx.x) >> 5);
    if (r >= n) return;
    int lane = threadIdx.x & 31;
    float4 h = ((const float4*)(HS + (size_t)r * 128))[lane];
    float4 a = ((const float4*)at)[lane];
    float p = h.x * a.x + h.y * a.y + h.z * a.z + h.w * a.w;
    p += __shfl_xor_sync(0xffffffffu, p, 4);
    p += __shfl_xor_sync(0xffffffffu, p, 2);
    p += __shfl_xor_sync(0xffffffffu, p, 1);
    if ((lane & 7) == 0) AS[r * 4 + (lane >> 3)] = p;
}

// ---------------- P2 = HS2 * attn2 (pointwise) ----------------
__global__ void p2K(const float* __restrict__ HS2, const float* __restrict__ at,
                    float* __restrict__ P2, int n4)
{
    int i = blockIdx.x * blockDim.x + threadIdx.x;
    if (i >= n4) return;
    float4 h = ((const float4*)HS2)[i];
    float4 a = ((const float4*)at)[i & 31];
    ((float4*)P2)[i] = make_float4(h.x * a.x, h.y * a.y, h.z * a.z, h.w * a.w);
}

// ---------------- passA t0: warp/edge, gated by GTA0 (attn folded) ----------------
__global__ void __launch_bounds__(256) passA0(
    const float* __restrict__ HS, const int* __restrict__ src, const int* __restrict__ dst,
    const int* __restrict__ cg, const float* __restrict__ AD,
    float* __restrict__ expv, float* __restrict__ seg, int E)
{
    int e = (int)((blockIdx.x * (size_t)blockDim.x + threadIdx.x) >> 5);
    if (e >= E) return;
    int lane = threadIdx.x & 31;
    int s = src[e], d = dst[e];
    float4 hs = ((const float4*)(HS + (size_t)s * 128))[lane];
    int a = cg[2 * e], b = cg[2 * e + 1];
    float4 g = ((const float4*)(g_GTA0 + (a * 8 + b) * 128))[lane];
    float p = hs.x * g.x + hs.y * g.y + hs.z * g.z + hs.w * g.w;
    p += __shfl_xor_sync(0xffffffffu, p, 4);
    p += __shfl_xor_sync(0xffffffffu, p, 2);
    p += __shfl_xor_sync(0xffffffffu, p, 1);
    float h0 = __shfl_sync(0xffffffffu, p, 0);
    float h1 = __shfl_sync(0xffffffffu, p, 8);
    float h2 = __shfl_sync(0xffffffffu, p, 16);
    float h3 = __shfl_sync(0xffffffffu, p, 24);
    if (lane == 0) {
        float4 ad = ((const float4*)AD)[d];
        float l0 = h0 + ad.x, l1 = h1 + ad.y, l2 = h2 + ad.z, l3 = h3 + ad.w;
        float4 ex;
        ex.x = expf(l0 > 0.f ? l0 : 0.2f * l0);
        ex.y = expf(l1 > 0.f ? l1 : 0.2f * l1);
        ex.z = expf(l2 > 0.f ? l2 : 0.2f * l2);
        ex.w = expf(l3 > 0.f ? l3 : 0.2f * l3);
        ((float4*)expv)[e] = ex;
        red_add_v4(seg + (size_t)d * 4, ex);
    }
}

// ---------------- passA t2: warp/edge, P2 . G2 ----------------
__global__ void __launch_bounds__(256) passA2(
    const float* __restrict__ P2, const int* __restrict__ src, const int* __restrict__ dst,
    const float* __restrict__ G2, const float* __restrict__ AD,
    float* __restrict__ expv, float* __restrict__ seg, int E)
{
    int e = (int)((blockIdx.x * (size_t)blockDim.x + threadIdx.x) >> 5);
    if (e >= E) return;
    int lane = threadIdx.x & 31;
    int s = src[e], d = dst[e];
    float4 hs = ((const float4*)(P2 + (size_t)s * 128))[lane];
    float4 g = ((const float4*)(G2 + (size_t)e * 128))[lane];
    float p = hs.x * g.x + hs.y * g.y + hs.z * g.z + hs.w * g.w;
    p += __shfl_xor_sync(0xffffffffu, p, 4);
    p += __shfl_xor_sync(0xffffffffu, p, 2);
    p += __shfl_xor_sync(0xffffffffu, p, 1);
    float h0 = __shfl_sync(0xffffffffu, p, 0);
    float h1 = __shfl_sync(0xffffffffu, p, 8);
    float h2 = __shfl_sync(0xffffffffu, p, 16);
    float h3 = __shfl_sync(0xffffffffu, p, 24);
    if (lane == 0) {
        float4 ad = ((const float4*)AD)[d];
        float l0 = h0 + ad.x, l1 = h1 + ad.y, l2 = h2 + ad.z, l3 = h3 + ad.w;
        float4 ex;
        ex.x = expf(l0 > 0.f ? l0 : 0.2f * l0);
        ex.y = expf(l1 > 0.f ? l1 : 0.2f * l1);
        ex.z = expf(l2 > 0.f ? l2 : 0.2f * l2);
        ex.w = expf(l3 > 0.f ? l3 : 0.2f * l3);
        ((float4*)expv)[e] = ex;
        red_add_v4(seg + (size_t)d * 4, ex);
    }
}

// ---------------- passA t1/t3: thread/edge via AS/AD ----------------
__global__ void __launch_bounds__(256) passAL(
    const float* __restrict__ AS, const int* __restrict__ src, const int* __restrict__ dst,
    const float* __restrict__ AD, float* __restrict__ expv, float* __restrict__ seg, int E)
{
    int e = blockIdx.x * blockDim.x + threadIdx.x;
    if (e >= E) return;
    float4 as = ((const float4*)AS)[src[e]];
    int d = dst[e];
    float4 ad = ((const float4*)AD)[d];
    float l0 = as.x + ad.x, l1 = as.y + ad.y, l2 = as.z + ad.z, l3 = as.w + ad.w;
    float4 ex;
    ex.x = expf(l0 > 0.f ? l0 : 0.2f * l0);
    ex.y = expf(l1 > 0.f ? l1 : 0.2f * l1);
    ex.z = expf(l2 > 0.f ? l2 : 0.2f * l2);
    ex.w = expf(l3 > 0.f ? l3 : 0.2f * l3);
    ((float4*)expv)[e] = ex;
    red_add_v4(seg + (size_t)d * 4, ex);
}

// ---------------- passB: alpha * gated_ms scattered into acc ----------------
__global__ void __launch_bounds__(256) passB(
    const float* __restrict__ HS,
    const int* __restrict__ src, const int* __restrict__ dst,
    const float* __restrict__ gate, const int* __restrict__ cg,
    const float* __restrict__ expv, const float* __restrict__ segsum,
    float* __restrict__ acc, int E)
{
    int e = (int)((blockIdx.x * (size_t)blockDim.x + threadIdx.x) >> 5);
    if (e >= E) return;
    int lane = threadIdx.x & 31;
    int s = src[e], d = dst[e];
    int h = lane >> 3;
    float al = expv[4 * e + h] / segsum[(size_t)d * 4 + h];
    float4 ms = ((const float4*)(HS + (size_t)s * 128))[lane];
    if (gate) {
        float4 g = ((const float4*)(gate + (size_t)e * 128))[lane];
        ms.x *= g.x; ms.y *= g.y; ms.z *= g.z; ms.w *= g.w;
    } else if (cg) {
        int a = cg[2 * e], b = cg[2 * e + 1];
        float4 g = ((const float4*)(g_GTAB + (a * 8 + b) * 128))[lane];
        ms.x *= g.x; ms.y *= g.y; ms.z *= g.z; ms.w *= g.w;
    }
    float4 o = make_float4(al * ms.x, al * ms.y, al * ms.z, al * ms.w);
    red_add_v4(acc + (size_t)d * 128 + lane * 4, o);
}

__global__ void biasfill(float* __restrict__ out, const float* __restrict__ b, int n)
{
    int i = blockIdx.x * blockDim.x + threadIdx.x;
    if (i < n * 128) out[i] = b[i & 127];
}

// ---------------- launch ----------------
extern "C" void kernel_launch(void* const* d_in, const int* in_sizes, int n_in,
                              void* d_out, int out_size)
{
    int iWsrc, ibsrc, iWdst, ibdst, iattn, itemb, isemb, iWg, ibg, iW1c, ib1c,
        iW2c, ib2c, iWout, ibout, icp, icg;
    int isrc[4], idst[4];
    if (in_sizes[4] == 65536) {            // layout A: Wsrc at slot 4
        iWsrc = 4; ibsrc = 5; iWdst = 6; ibdst = 7; iattn = 8; itemb = 9; isemb = 10;
        iWg = 11; ibg = 12; iW1c = 13; ib1c = 14; iW2c = 15; ib2c = 16;
        iWout = 17; ibout = 18; icp = 19;
        isrc[0] = 20; idst[0] = 21; isrc[1] = 22; idst[1] = 23;
        isrc[2] = 24; idst[2] = 25; isrc[3] = 26; idst[3] = 27; icg = 28;
    } else {                               // layout B: src0 at slot 4
        isrc[0] = 4; idst[0] = 5; isrc[1] = 6; idst[1] = 7;
        isrc[2] = 8; idst[2] = 9; isrc[3] = 10; idst[3] = 11;
        icg = 12; icp = 13;
        iWsrc = 14; ibsrc = 15; iWdst = 16; ibdst = 17; iattn = 18;
        itemb = 19; isemb = 20; iWg = 21; ibg = 22; iW1c = 23; ib1c = 24;
        iW2c = 25; ib2c = 26; iWout = 27; ibout = 28;
    }

    const float* x[4]  = {(const float*)d_in[0], (const float*)d_in[1],
                          (const float*)d_in[2], (const float*)d_in[3]};
    const float* Wsrc  = (const float*)d_in[iWsrc];
    const float* bsrc  = (const float*)d_in[ibsrc];
    const float* Wdst  = (const float*)d_in[iWdst];
    const float* bdst  = (const float*)d_in[ibdst];
    const float* attn  = (const float*)d_in[iattn];
    const float* temb  = (const float*)d_in[itemb];
    const float* semb  = (const float*)d_in[isemb];
    const float* Wg    = (const float*)d_in[iWg];
    const float* bg    = (const float*)d_in[ibg];
    const float* W1c   = (const float*)d_in[iW1c];
    const float* b1c   = (const float*)d_in[ib1c];
    const float* W2c   = (const float*)d_in[iW2c];
    const float* b2c   = (const float*)d_in[ib2c];
    const float* Wout  = (const float*)d_in[iWout];
    const float* bout  = (const float*)d_in[ibout];
    const float* cp    = (const float*)d_in[icp];
    const int* srcp[4] = {(const int*)d_in[isrc[0]], (const int*)d_in[isrc[1]],
                          (const int*)d_in[isrc[2]], (const int*)d_in[isrc[3]]};
    const int* dstp[4] = {(const int*)d_in[idst[0]], (const int*)d_in[idst[1]],
                          (const int*)d_in[idst[2]], (const int*)d_in[idst[3]]};
    const int* cg      = (const int*)d_in[icg];
    float* out = (float*)d_out;

    int Nn[4] = {in_sizes[0] / 128, in_sizes[1] / 128, in_sizes[2] / 128, in_sizes[3] / 128};
    int Ee[4] = {in_sizes[isrc[0]], in_sizes[isrc[1]], in_sizes[isrc[2]], in_sizes[isrc[3]]};
    int sidx[4] = {0, 1, 0, 2};
    int didx[4] = {1, 0, 3, 1};

    float *H, *G2, *P2, *EXPV, *SEG, *ACC, *AS, *AD, *WA, *BA;
    __nv_bfloat16 *WTh, *WTl;
    cudaGetSymbolAddress((void**)&H, g_H);
    cudaGetSymbolAddress((void**)&G2, g_G2);
    cudaGetSymbolAddress((void**)&P2, g_P2);
    cudaGetSymbolAddress((void**)&EXPV, g_EXPV);
    cudaGetSymbolAddress((void**)&SEG, g_SEG);
    cudaGetSymbolAddress((void**)&ACC, g_ACC);
    cudaGetSymbolAddress((void**)&AS, g_AS);
    cudaGetSymbolAddress((void**)&AD, g_AD);
    cudaGetSymbolAddress((void**)&WA, g_WA);
    cudaGetSymbolAddress((void**)&BA, g_BA);
    cudaGetSymbolAddress((void**)&WTh, g_WTh);
    cudaGetSymbolAddress((void**)&WTl, g_WTl);

    cudaFuncSetAttribute(mm_gemm, cudaFuncAttributeMaxDynamicSharedMemorySize, DYN_SMEM);
    cudaFuncSetAttribute(mm_gate, cudaFuncAttributeMaxDynamicSharedMemorySize, DYN_SMEM);

    size_t hofs[4] = {0, 50000, 80000, 130000};
    float* HSp[4] = {H, H + hofs[1] * 128, H + hofs[2] * 128, H + hofs[3] * 128};
    float* EXP_t[4] = {EXPV, EXPV + 2000000, EXPV + 4000000, EXPV + 5000000};
    float* SEG_t[4] = {SEG, SEG + 200000, SEG + 400000, SEG + 600000};
    float* AD_t[4]  = {AD, AD + 200000, AD + 400000, AD + 600000};
    float* accp[4];
    accp[0] = ACC;
    accp[1] = ACC + (size_t)Nn[0] * 128;
    accp[2] = nullptr;
    accp[3] = ACC + (size_t)(Nn[0] + Nn[1]) * 128;
    float* accd[4] = {accp[1], accp[0], accp[3], accp[1]};

    // 1. weight prep
    WList wl;
    wl.w[0] = Wsrc;             wl.w[1] = Wsrc + 16384;
    wl.w[2] = Wsrc + 2 * 16384; wl.w[3] = Wsrc + 3 * 16384;
    wl.w[4] = Wout;             wl.w[5] = Wout + 16384;
    wl.w[6] = Wout + 3 * 16384; wl.w[7] = W2c;
    prep_w<<<dim3(8, 64), 256>>>(wl);
    prep_wa<<<4, 128>>>(Wdst, bdst, attn);
    gtabk<<<80, 128>>>(temb, semb, Wg, bg, attn);

    // 2. source transforms (batched wmma GEMM)
    Segs T;
    T.nseg = 4;
    int tcum = 0;
    for (int t = 0; t < 4; t++) {
        int ns = Nn[sidx[t]];
        T.s[t].X = x[sidx[t]];
        T.s[t].Bh = WTh + t * 16384;
        T.s[t].Bl = WTl + t * 16384;
        T.s[t].bias = bsrc + t * 128;
        T.s[t].Y = HSp[t];
        T.s[t].nrows = ns;
        T.s[t].tofs = tcum;
        tcum += (ns + 127) / 128;
    }
    mm_gemm<<<tcum, 256, DYN_SMEM>>>(T);

    // 3. continuous gate
    mm_gate<<<(Ee[2] + 127) / 128, 256, DYN_SMEM>>>(cp, W1c, b1c,
        WTh + 7 * 16384, WTl + 7 * 16384, b2c, G2, Ee[2]);

    // 4. attn precomputes
    p2K<<<(Nn[0] * 32 + 255) / 256, 256>>>(HSp[2], attn + 2 * 128, P2, Nn[0] * 32);
    asK<<<(Nn[1] * 32 + 255) / 256, 256>>>(HSp[1], attn + 1 * 128, AS, Nn[1]);
    asK<<<(Nn[2] * 32 + 255) / 256, 256>>>(HSp[3], attn + 3 * 128, AS + 200000, Nn[2]);
    for (int t = 0; t < 4; t++) {
        int nd = Nn[didx[t]];
        adK<<<(nd * 32 + 255) / 256, 256>>>(x[didx[t]], WA + t * 512, BA + t * 4, AD_t[t], nd);
    }

    // 5. zero segment sums + accumulators
    cudaMemsetAsync(SEG, 0, 4 * 200000 * sizeof(float));
    cudaMemsetAsync(ACC, 0, (size_t)(Nn[0] + Nn[1] + Nn[3]) * 128 * sizeof(float));

    // 6. passA
    passA0<<<(Ee[0] + 7) / 8, 256>>>(HSp[0], srcp[0], dstp[0], cg, AD_t[0],
                                     EXP_t[0], SEG_t[0], Ee[0]);
    passAL<<<(Ee[1] + 255) / 256, 256>>>(AS, srcp[1], dstp[1], AD_t[1],
                                         EXP_t[1], SEG_t[1], Ee[1]);
    passA2<<<(Ee[2] + 7) / 8, 256>>>(P2, srcp[2], dstp[2], G2, AD_t[2],
                                     EXP_t[2], SEG_t[2], Ee[2]);
    passAL<<<(Ee[3] + 255) / 256, 256>>>(AS + 200000, srcp[3], dstp[3], AD_t[3],
                                         EXP_t[3], SEG_t[3], Ee[3]);

    // 7. passB
    for (int t = 0; t < 4; t++) {
        const float* gate = (t == 2) ? G2 : nullptr;
        const int* cgp = (t == 0) ? cg : nullptr;
        passB<<<(Ee[t] + 7) / 8, 256>>>(HSp[t], srcp[t], dstp[t], gate, cgp,
                                        EXP_t[t], SEG_t[t], accd[t], Ee[t]);
    }

    // 8. output GEMMs
    float* o_chem = out;
    float* o_gene = o_chem + (size_t)Nn[0] * 128;
    float* o_dis  = o_gene + (size_t)Nn[1] * 128;
    float* o_path = o_dis + (size_t)Nn[2] * 128;
    Segs O;
    O.nseg = 3;
    O.s[0] = {accp[0], WTh + 4 * 16384, WTl + 4 * 16384, bout,       o_chem, Nn[0], 0};
    int t1 = (Nn[0] + 127) / 128;
    O.s[1] = {accp[1], WTh + 5 * 16384, WTl + 5 * 16384, bout + 128, o_gene, Nn[1], t1};
    int t2 = t1 + (Nn[1] + 127) / 128;
    O.s[2] = {accp[3], WTh + 6 * 16384, WTl + 6 * 16384, bout + 384, o_path, Nn[3], t2};
    int t3 = t2 + (Nn[3] + 127) / 128;
    mm_gemm<<<t3, 256, DYN_SMEM>>>(O);
    biasfill<<<(Nn[2] * 128 + 255) / 256, 256>>>(o_dis, bout + 256, Nn[2]);
}